// round 7
// baseline (speedup 1.0000x reference)
#include <cuda_runtime.h>
#include <cstdint>

// Screen / tiling constants (W=1280, H=720 are exact multiples of L=16)
#define W_SCREEN 1280.0f
#define H_SCREEN 720.0f
#define NBW      80
#define NBH      45
#define N_POINTS 32768
#define ROWS_PER_BAND 9        // 45 = 5 * 9
#define BANDS     5
#define N_CHUNKS  64           // 512 points per chunk
#define SLOTS     37           // 64 * 37 = 2368 = 148 SMs * 16 CTAs (one wave)
#define N_ITEMS   (NBW * BANDS)   // 400 (xi, band) items per chunk

// Persistent single-wave kernel. Each CTA owns one 512-point chunk: loads the
// points ONCE, computes per-point tile intervals ONCE:
//   x: [ax0, ax0+nx] tile columns,  y: [a, a+n) tile rows
// then loops over the chunk's 400 (xi, band) work items with stride SLOTS.
// Per item: fold the x-test into n (one range-compare per point), then write
// 9 rows of one float4 (STG.128) each.
//
// Reference condition per (tile, point):
//   min(xmax,right) > max(xmin,left) && min(ymax,bottom) > max(ymin,top)
// With right=left+16, bottom=top+16 exact (W,H multiples of 16) and
// xmax>xmin, ymax>ymin guaranteed (radius >= 1), this is the separable test:
//   x: (unsigned)(xi - ax0) <= nx,   y: (unsigned)(yi - a) < n.
__global__ __launch_bounds__(128) void persistent_mask_kernel(
        const float* __restrict__ pos2d,
        const float* __restrict__ radius,
        float* __restrict__ out) {
    int t     = threadIdx.x;                 // 0..127
    int chunk = blockIdx.x;                  // 0..63
    int slot  = blockIdx.y;                  // 0..36

    int g = chunk * 128 + t;                 // 4-point group, 0..8191

    // Load this thread's 4 points (48 bytes, coalesced, read once per CTA).
    float4 q01 = reinterpret_cast<const float4*>(pos2d)[2 * g];      // pts 4g,4g+1
    float4 q23 = reinterpret_cast<const float4*>(pos2d)[2 * g + 1];  // pts 4g+2,4g+3
    float4 r4  = reinterpret_cast<const float4*>(radius)[g];

    unsigned a[4], n[4], ax0[4], nx[4];
    {
        float xs[4] = {q01.x, q01.z, q23.x, q23.z};
        float ys[4] = {q01.y, q01.w, q23.y, q23.w};
        float rs[4] = {r4.x, r4.y, r4.z, r4.w};
#pragma unroll
        for (int j = 0; j < 4; j++) {
            float x = xs[j], y = ys[j], r = rs[j];
            int xmin = (int)fminf(fmaxf(x - r, 0.0f), W_SCREEN);
            int xmax = (int)fminf(fmaxf(x + r, 0.0f), W_SCREEN);
            int ymin = (int)fminf(fmaxf(y - r, 0.0f), H_SCREEN);
            int ymax = (int)fminf(fmaxf(y + r, 0.0f), H_SCREEN);

            ax0[j] = (unsigned)(xmin >> 4);                  // first valid xi
            nx[j]  = (unsigned)((xmax - 1) >> 4) - ax0[j];   // last - first (>=0)
            a[j]   = (unsigned)(ymin >> 4);                  // first valid yi
            n[j]   = (unsigned)(((ymax - 1) >> 4) + 1) - a[j]; // y-interval length
        }
    }

    float* base = out + (size_t)g * 4;

    for (int item = slot; item < N_ITEMS; item += SLOTS) {
        int xi = item / BANDS;
        int y0 = (item - xi * BANDS) * ROWS_PER_BAND;

        // Fold x-validity: n_eff = in-x-range ? n : 0.
        unsigned n0 = ((unsigned)(xi - ax0[0]) <= nx[0]) ? n[0] : 0u;
        unsigned n1 = ((unsigned)(xi - ax0[1]) <= nx[1]) ? n[1] : 0u;
        unsigned n2 = ((unsigned)(xi - ax0[2]) <= nx[2]) ? n[2] : 0u;
        unsigned n3 = ((unsigned)(xi - ax0[3]) <= nx[3]) ? n[3] : 0u;

        float* optr = base + ((size_t)xi * NBH + y0) * N_POINTS;

#pragma unroll
        for (int k = 0; k < ROWS_PER_BAND; k++) {
            int yi = y0 + k;
            float4 v;
            v.x = ((unsigned)(yi - a[0]) < n0) ? 1.0f : 0.0f;
            v.y = ((unsigned)(yi - a[1]) < n1) ? 1.0f : 0.0f;
            v.z = ((unsigned)(yi - a[2]) < n2) ? 1.0f : 0.0f;
            v.w = ((unsigned)(yi - a[3]) < n3) ? 1.0f : 0.0f;
            *reinterpret_cast<float4*>(optr) = v;
            optr += N_POINTS;
        }
    }
}

extern "C" void kernel_launch(void* const* d_in, const int* in_sizes, int n_in,
                              void* d_out, int out_size) {
    const float* pos2d  = (const float*)d_in[0];   // [32768, 2] float32
    const float* radius = (const float*)d_in[1];   // [32768]    float32
    float* out          = (float*)d_out;           // [3600, 32768] float32

    dim3 grid(N_CHUNKS, SLOTS);                    // 64 x 37 = 2368 CTAs (1 wave)
    persistent_mask_kernel<<<grid, 128>>>(pos2d, radius, out);
}

// round 9
// speedup vs baseline: 1.0588x; 1.0588x over previous
#include <cuda_runtime.h>
#include <cstdint>

// Screen / tiling constants (W=1280, H=720 are exact multiples of L=16)
#define W_SCREEN 1280.0f
#define H_SCREEN 720.0f
#define NBW      80
#define NBH      45
#define N_POINTS 32768
#define ROWS_PER_CTA 9     // 45 = 5 * 9
#define BANDS     5

// Per-point tile intervals packed into one uint32:
//   byte0 = a   (first valid yi, 0..44)
//   byte1 = n   (y-interval length, 0..45)
//   byte2 = ax0 (first valid xi, 0..79)
//   byte3 = nx  (last-first xi, 0..79)
__device__ __align__(16) unsigned g_packed[N_POINTS];

// Kernel 1 (tiny): per-point AABB -> packed tile intervals.
// Mirrors reference create_tiles; with right=left+16, bottom=top+16 exact and
// xmax>xmin, ymax>ymin guaranteed (radius >= 1), the overlap test is the
// separable test  (unsigned)(xi-ax0) <= nx  &&  (unsigned)(yi-a) < n.
__global__ void prep_kernel(const float* __restrict__ pos2d,
                            const float* __restrict__ radius) {
    int i = blockIdx.x * blockDim.x + threadIdx.x;
    if (i >= N_POINTS) return;
    float x = pos2d[2 * i];
    float y = pos2d[2 * i + 1];
    float r = radius[i];
    int xmin = (int)fminf(fmaxf(x - r, 0.0f), W_SCREEN);
    int xmax = (int)fminf(fmaxf(x + r, 0.0f), W_SCREEN);
    int ymin = (int)fminf(fmaxf(y - r, 0.0f), H_SCREEN);
    int ymax = (int)fminf(fmaxf(y + r, 0.0f), H_SCREEN);

    unsigned a   = (unsigned)(ymin >> 4);
    unsigned n   = (unsigned)(((ymax - 1) >> 4) + 1) - a;
    unsigned ax0 = (unsigned)(xmin >> 4);
    unsigned nx  = (unsigned)((xmax - 1) >> 4) - ax0;

    g_packed[i] = a | (n << 8) | (ax0 << 16) | (nx << 24);
}

// Kernel 2: R5 work partition — one block per (512-point chunk, xi column,
// 9-row band); each thread owns 4 consecutive points. Prolog is now a single
// LDG.128 of packed intervals + byte extraction (no FP), then the band sweep
// emits one float4 (STG.128) per row.
__global__ __launch_bounds__(128) void mask_kernel(float* __restrict__ out) {
    int g  = blockIdx.x * 128 + threadIdx.x;   // 4-point group, 0..8191
    int xi = blockIdx.y;                       // 0..79
    int y0 = blockIdx.z * ROWS_PER_CTA;        // 0, 9, 18, 27, 36

    uint4 pk = reinterpret_cast<const uint4*>(g_packed)[g];

    unsigned a[4], n[4];
    {
        unsigned w[4] = {pk.x, pk.y, pk.z, pk.w};
#pragma unroll
        for (int j = 0; j < 4; j++) {
            unsigned aj  = w[j] & 0xFFu;
            unsigned nj  = (w[j] >> 8) & 0xFFu;
            unsigned ax0 = (w[j] >> 16) & 0xFFu;
            unsigned nx  = w[j] >> 24;
            a[j] = aj;
            n[j] = ((unsigned)(xi - ax0) <= nx) ? nj : 0u;  // fold x-validity
        }
    }

    float* optr = out + ((size_t)xi * NBH + y0) * N_POINTS + (size_t)g * 4;

#pragma unroll
    for (int k = 0; k < ROWS_PER_CTA; k++) {
        int yi = y0 + k;
        float4 v;
        v.x = ((unsigned)(yi - a[0]) < n[0]) ? 1.0f : 0.0f;
        v.y = ((unsigned)(yi - a[1]) < n[1]) ? 1.0f : 0.0f;
        v.z = ((unsigned)(yi - a[2]) < n[2]) ? 1.0f : 0.0f;
        v.w = ((unsigned)(yi - a[3]) < n[3]) ? 1.0f : 0.0f;
        *reinterpret_cast<float4*>(optr) = v;
        optr += N_POINTS;
    }
}

extern "C" void kernel_launch(void* const* d_in, const int* in_sizes, int n_in,
                              void* d_out, int out_size) {
    const float* pos2d  = (const float*)d_in[0];   // [32768, 2] float32
    const float* radius = (const float*)d_in[1];   // [32768]    float32
    float* out          = (float*)d_out;           // [3600, 32768] float32

    prep_kernel<<<128, 256>>>(pos2d, radius);
    dim3 grid(64, NBW, BANDS);                     // 64 chunks x 80 xi x 5 bands
    mask_kernel<<<grid, 128>>>(out);
}